// round 3
// baseline (speedup 1.0000x reference)
#include <cuda_runtime.h>

#define CDIV(a,b) (((a)+(b)-1)/(b))

static const int MAXN = 100000;
static const int MAXE = 1600000;

// ---------------- scratch (device globals; no allocation) ----------------
// 16-byte alignment REQUIRED: accessed via float4 loads/stores.
__device__ int   g_src[MAXE];
__device__ int   g_dst[MAXE];
__device__ __align__(16) float g_y1[MAXN*32];
__device__ __align__(16) float g_z1[MAXN*32];
__device__ __align__(16) float g_agg1[MAXN*32];
__device__ __align__(16) float g_y2[MAXN*48];
__device__ __align__(16) float g_z2[MAXN*48];
__device__ __align__(16) float g_agg2[MAXN*48];
__device__ __align__(16) float g_y3[MAXN*16];
__device__ __align__(16) float g_z3[MAXN*16];
__device__ __align__(16) float g_agg3[MAXN*16];

// ---------------- index load: int32 edge_index, clamped ----------------
// JAX default config produces int32 for edge_index (x64 disabled), so the
// buffer is 2*E int32. Clamp defensively: a wrong-dtype assumption then
// shows up as rel_err, not an illegal access.
__global__ void convert_idx_kernel(const int* __restrict__ ei, int E, int n) {
    int t = blockIdx.x * blockDim.x + threadIdx.x;
    if (t < E) {
        int s = ei[t];
        int d = ei[E + t];
        g_src[t] = min(max(s, 0), n - 1);
        g_dst[t] = min(max(d, 0), n - 1);
    }
}

// ---------------- fused GEMM: y = h@Wrel, z = h@Wroot + b, agg = 0 -------
// h = [ (RELUA ? relu(A + A2) : A) | B ]  per node, widths INA / INB.
template<int INA, int INB, int OUT, bool RELUA>
__device__ __forceinline__ void gemm_body(
    const float* __restrict__ A, const float* __restrict__ A2,
    const float* __restrict__ B,
    const float* __restrict__ Wr, const float* __restrict__ Wo,
    const float* __restrict__ bias,
    float* __restrict__ y, float* __restrict__ z, float* __restrict__ agg,
    int n_nodes)
{
    constexpr int IN = INA + INB;
    __shared__ float sWr[IN * OUT];
    __shared__ float sWz[IN * OUT];
    __shared__ float sB[OUT];
    for (int i = threadIdx.x; i < IN * OUT; i += 128) {
        sWr[i] = Wr[i];
        sWz[i] = Wo[i];
    }
    if (threadIdx.x < OUT) sB[threadIdx.x] = bias[threadIdx.x];
    __syncthreads();

    int n = blockIdx.x * 128 + threadIdx.x;
    if (n >= n_nodes) return;

    float h[IN];
#pragma unroll
    for (int c = 0; c < INA / 4; c++) {
        float4 v = __ldg((const float4*)A + n * (INA / 4) + c);
        if constexpr (RELUA) {
            float4 w = __ldg((const float4*)A2 + n * (INA / 4) + c);
            v.x = fmaxf(v.x + w.x, 0.f);
            v.y = fmaxf(v.y + w.y, 0.f);
            v.z = fmaxf(v.z + w.z, 0.f);
            v.w = fmaxf(v.w + w.w, 0.f);
        }
        h[4*c+0] = v.x; h[4*c+1] = v.y; h[4*c+2] = v.z; h[4*c+3] = v.w;
    }
    if constexpr (INB > 0) {
#pragma unroll
        for (int c = 0; c < INB / 4; c++) {
            float4 v = __ldg((const float4*)B + n * (INB / 4) + c);
            h[INA+4*c+0] = v.x; h[INA+4*c+1] = v.y;
            h[INA+4*c+2] = v.z; h[INA+4*c+3] = v.w;
        }
    }

    for (int o4 = 0; o4 < OUT / 4; o4++) {
        float4 ar = make_float4(0.f, 0.f, 0.f, 0.f);
        float4 az = *(const float4*)&sB[o4 * 4];
#pragma unroll
        for (int k = 0; k < IN; k++) {
            float4 wr = *(const float4*)&sWr[k * OUT + o4 * 4];
            float4 wz = *(const float4*)&sWz[k * OUT + o4 * 4];
            ar.x = fmaf(h[k], wr.x, ar.x);
            ar.y = fmaf(h[k], wr.y, ar.y);
            ar.z = fmaf(h[k], wr.z, ar.z);
            ar.w = fmaf(h[k], wr.w, ar.w);
            az.x = fmaf(h[k], wz.x, az.x);
            az.y = fmaf(h[k], wz.y, az.y);
            az.z = fmaf(h[k], wz.z, az.z);
            az.w = fmaf(h[k], wz.w, az.w);
        }
        ((float4*)y)[n * (OUT / 4) + o4] = ar;
        ((float4*)z)[n * (OUT / 4) + o4] = az;
        ((float4*)agg)[n * (OUT / 4) + o4] = make_float4(0.f, 0.f, 0.f, 0.f);
    }
}

__global__ void __launch_bounds__(128) gemm1_kernel(
    const float* __restrict__ x, const float* __restrict__ ax,
    const float* __restrict__ Wr, const float* __restrict__ Wo,
    const float* __restrict__ b, int n_nodes)
{
    gemm_body<48, 16, 32, false>(x, nullptr, ax, Wr, Wo, b,
                                 g_y1, g_z1, g_agg1, n_nodes);
}

__global__ void __launch_bounds__(128) gemm2_kernel(
    const float* __restrict__ lf,
    const float* __restrict__ Wr, const float* __restrict__ Wo,
    const float* __restrict__ b, int n_nodes)
{
    gemm_body<32, 16, 48, true>(g_agg1, g_z1, lf, Wr, Wo, b,
                                g_y2, g_z2, g_agg2, n_nodes);
}

__global__ void __launch_bounds__(128) gemm3_kernel(
    const float* __restrict__ Wr, const float* __restrict__ Wo,
    const float* __restrict__ b, int n_nodes)
{
    gemm_body<48, 0, 16, true>(g_agg2, g_z2, nullptr, Wr, Wo, b,
                               g_y3, g_z3, g_agg3, n_nodes);
}

// ---------------- edge scatter: agg[dst] += y[src] ----------------
// Thread = (edge, float4 chunk). Consecutive threads cover one edge's
// contiguous row -> coalesced gather; atomics hit L2-resident agg table.
template<int D4>
__device__ __forceinline__ void scatter_body(const float* __restrict__ y,
                                             float* __restrict__ agg, int E)
{
    int t = blockIdx.x * blockDim.x + threadIdx.x;
    if (t >= E * D4) return;
    int e = t / D4;
    int c = t - e * D4;
    int s = g_src[e];
    int d = g_dst[e];
    float4 v = __ldg((const float4*)y + s * D4 + c);
    float* a = agg + (d * D4 + c) * 4;
    atomicAdd(a + 0, v.x);
    atomicAdd(a + 1, v.y);
    atomicAdd(a + 2, v.z);
    atomicAdd(a + 3, v.w);
}

__global__ void scatter1_kernel(int E) { scatter_body<8 >(g_y1, g_agg1, E); }
__global__ void scatter2_kernel(int E) { scatter_body<12>(g_y2, g_agg2, E); }
__global__ void scatter3_kernel(int E) { scatter_body<4 >(g_y3, g_agg3, E); }

// ---------------- final: out = agg3 + z3 + additional_x ----------------
__global__ void final_kernel(const float* __restrict__ ax,
                             float* __restrict__ out, int n_nodes)
{
    int t = blockIdx.x * blockDim.x + threadIdx.x;
    if (t >= n_nodes * 4) return;
    float4 a = ((const float4*)g_agg3)[t];
    float4 z = ((const float4*)g_z3)[t];
    float4 x = __ldg((const float4*)ax + t);
    ((float4*)out)[t] = make_float4(a.x + z.x + x.x,
                                    a.y + z.y + x.y,
                                    a.z + z.z + x.z,
                                    a.w + z.w + x.w);
}

// ---------------- launch ----------------
extern "C" void kernel_launch(void* const* d_in, const int* in_sizes, int n_in,
                              void* d_out, int out_size)
{
    (void)n_in; (void)out_size;
    const float* x   = (const float*)d_in[0];
    const int*   ei  = (const int*)d_in[1];     // int32 (JAX x64 disabled)
    const float* ax  = (const float*)d_in[2];
    const float* lf  = (const float*)d_in[3];
    const float* W1r = (const float*)d_in[4];
    const float* b1  = (const float*)d_in[5];
    const float* W1o = (const float*)d_in[6];
    const float* W2r = (const float*)d_in[7];
    const float* b2  = (const float*)d_in[8];
    const float* W2o = (const float*)d_in[9];
    const float* W3r = (const float*)d_in[10];
    const float* b3  = (const float*)d_in[11];
    const float* W3o = (const float*)d_in[12];

    int N = in_sizes[0] / 48;
    int E = in_sizes[1] / 2;

    convert_idx_kernel<<<CDIV(E, 256), 256>>>(ei, E, N);

    gemm1_kernel<<<CDIV(N, 128), 128>>>(x, ax, W1r, W1o, b1, N);
    scatter1_kernel<<<CDIV(E * 8, 256), 256>>>(E);

    gemm2_kernel<<<CDIV(N, 128), 128>>>(lf, W2r, W2o, b2, N);
    scatter2_kernel<<<CDIV(E * 12, 256), 256>>>(E);

    gemm3_kernel<<<CDIV(N, 128), 128>>>(W3r, W3o, b3, N);
    scatter3_kernel<<<CDIV(E * 4, 256), 256>>>(E);

    final_kernel<<<CDIV(N * 4, 256), 256>>>(ax, (float*)d_out, N);
}

// round 4
// speedup vs baseline: 1.2575x; 1.2575x over previous
#include <cuda_runtime.h>

#define CDIV(a,b) (((a)+(b)-1)/(b))

static const int MAXN = 100000;
static const int MAXE = 1600000;

// ---------------- scratch (device globals; no allocation) ----------------
__device__ int g_cnt[MAXN];
__device__ int g_rs[MAXN + 1];   // CSR row start (by dst)
__device__ int g_wp[MAXN];       // fill write pointers
__device__ int g_csrc[MAXE];     // src node id per CSR slot

__device__ __align__(16) float g_y1[MAXN*32];
__device__ __align__(16) float g_z1[MAXN*32];
__device__ __align__(16) float g_agg1[MAXN*32];
__device__ __align__(16) float g_y2[MAXN*48];
__device__ __align__(16) float g_z2[MAXN*48];
__device__ __align__(16) float g_agg2[MAXN*48];
__device__ __align__(16) float g_y3[MAXN*16];
__device__ __align__(16) float g_z3[MAXN*16];

// ---------------- CSR build ----------------
__global__ void zero_cnt_kernel(int N) {
    int t = blockIdx.x * blockDim.x + threadIdx.x;
    if (t < N) g_cnt[t] = 0;
}

__global__ void count_kernel(const int* __restrict__ ei, int E, int N) {
    int t = blockIdx.x * blockDim.x + threadIdx.x;
    if (t < E) {
        int d = min(max(ei[E + t], 0), N - 1);
        atomicAdd(&g_cnt[d], 1);
    }
}

// Single-block exclusive scan over g_cnt -> g_rs / g_wp.
__global__ void __launch_bounds__(1024) scan_kernel(int N, int E) {
    __shared__ int ssum[1024];
    int tid = threadIdx.x;
    int chunk = (N + 1023) / 1024;
    int b = tid * chunk;
    int e = min(b + chunk, N);
    int s = 0;
    for (int j = b; j < e; j++) s += g_cnt[j];
    ssum[tid] = s;
    __syncthreads();
    for (int off = 1; off < 1024; off <<= 1) {
        int t = (tid >= off) ? ssum[tid - off] : 0;
        __syncthreads();
        ssum[tid] += t;
        __syncthreads();
    }
    int run = ssum[tid] - s;   // exclusive offset of this chunk
    for (int j = b; j < e; j++) {
        g_rs[j] = run;
        g_wp[j] = run;
        run += g_cnt[j];
    }
    if (tid == 1023) g_rs[N] = E;
}

__global__ void fill_kernel(const int* __restrict__ ei, int E, int N) {
    int t = blockIdx.x * blockDim.x + threadIdx.x;
    if (t < E) {
        int s = min(max(ei[t], 0), N - 1);
        int d = min(max(ei[E + t], 0), N - 1);
        int p = atomicAdd(&g_wp[d], 1);
        g_csrc[p] = s;
    }
}

// ---------------- fused GEMM: y = h@Wrel, z = h@Wroot + b ----------------
// h = [ (RELUA ? relu(A + A2) : A) | B ]  per node, widths INA / INB.
template<int INA, int INB, int OUT, bool RELUA>
__device__ __forceinline__ void gemm_body(
    const float* __restrict__ A, const float* __restrict__ A2,
    const float* __restrict__ B,
    const float* __restrict__ Wr, const float* __restrict__ Wo,
    const float* __restrict__ bias,
    float* __restrict__ y, float* __restrict__ z,
    int n_nodes)
{
    constexpr int IN = INA + INB;
    __shared__ float sWr[IN * OUT];
    __shared__ float sWz[IN * OUT];
    __shared__ float sB[OUT];
    for (int i = threadIdx.x; i < IN * OUT; i += 128) {
        sWr[i] = Wr[i];
        sWz[i] = Wo[i];
    }
    if (threadIdx.x < OUT) sB[threadIdx.x] = bias[threadIdx.x];
    __syncthreads();

    int n = blockIdx.x * 128 + threadIdx.x;
    if (n >= n_nodes) return;

    float h[IN];
#pragma unroll
    for (int c = 0; c < INA / 4; c++) {
        float4 v = __ldg((const float4*)A + n * (INA / 4) + c);
        if constexpr (RELUA) {
            float4 w = __ldg((const float4*)A2 + n * (INA / 4) + c);
            v.x = fmaxf(v.x + w.x, 0.f);
            v.y = fmaxf(v.y + w.y, 0.f);
            v.z = fmaxf(v.z + w.z, 0.f);
            v.w = fmaxf(v.w + w.w, 0.f);
        }
        h[4*c+0] = v.x; h[4*c+1] = v.y; h[4*c+2] = v.z; h[4*c+3] = v.w;
    }
    if constexpr (INB > 0) {
#pragma unroll
        for (int c = 0; c < INB / 4; c++) {
            float4 v = __ldg((const float4*)B + n * (INB / 4) + c);
            h[INA+4*c+0] = v.x; h[INA+4*c+1] = v.y;
            h[INA+4*c+2] = v.z; h[INA+4*c+3] = v.w;
        }
    }

    for (int o4 = 0; o4 < OUT / 4; o4++) {
        float4 ar = make_float4(0.f, 0.f, 0.f, 0.f);
        float4 az = *(const float4*)&sB[o4 * 4];
#pragma unroll
        for (int k = 0; k < IN; k++) {
            float4 wr = *(const float4*)&sWr[k * OUT + o4 * 4];
            float4 wz = *(const float4*)&sWz[k * OUT + o4 * 4];
            ar.x = fmaf(h[k], wr.x, ar.x);
            ar.y = fmaf(h[k], wr.y, ar.y);
            ar.z = fmaf(h[k], wr.z, ar.z);
            ar.w = fmaf(h[k], wr.w, ar.w);
            az.x = fmaf(h[k], wz.x, az.x);
            az.y = fmaf(h[k], wz.y, az.y);
            az.z = fmaf(h[k], wz.z, az.z);
            az.w = fmaf(h[k], wz.w, az.w);
        }
        ((float4*)y)[n * (OUT / 4) + o4] = ar;
        ((float4*)z)[n * (OUT / 4) + o4] = az;
    }
}

__global__ void __launch_bounds__(128) gemm1_kernel(
    const float* __restrict__ x, const float* __restrict__ ax,
    const float* __restrict__ Wr, const float* __restrict__ Wo,
    const float* __restrict__ b, int n_nodes)
{
    gemm_body<48, 16, 32, false>(x, nullptr, ax, Wr, Wo, b,
                                 g_y1, g_z1, n_nodes);
}

__global__ void __launch_bounds__(128) gemm2_kernel(
    const float* __restrict__ lf,
    const float* __restrict__ Wr, const float* __restrict__ Wo,
    const float* __restrict__ b, int n_nodes)
{
    gemm_body<32, 16, 48, true>(g_agg1, g_z1, lf, Wr, Wo, b,
                                g_y2, g_z2, n_nodes);
}

__global__ void __launch_bounds__(128) gemm3_kernel(
    const float* __restrict__ Wr, const float* __restrict__ Wo,
    const float* __restrict__ b, int n_nodes)
{
    gemm_body<48, 0, 16, true>(g_agg2, g_z2, nullptr, Wr, Wo, b,
                               g_y3, g_z3, n_nodes);
}

// ---------------- CSR gather: agg[n] = sum_{e in rows(n)} y[csrc[e]] -----
// Thread = (node, float4 chunk). Index loads broadcast across the D4
// threads of a node; gathers are independent 16B L2 reads (4-deep MLP).
template<int D4, bool FINAL>
__device__ __forceinline__ void gather_body(
    const float* __restrict__ y, float* __restrict__ outp,
    const float* __restrict__ z, const float* __restrict__ ax, int N)
{
    int t = blockIdx.x * blockDim.x + threadIdx.x;
    if (t >= N * D4) return;
    int n = t / D4;
    int c = t - n * D4;
    int e   = g_rs[n];
    int end = g_rs[n + 1];
    float4 acc = make_float4(0.f, 0.f, 0.f, 0.f);
    for (; e + 4 <= end; e += 4) {
        int s0 = g_csrc[e+0], s1 = g_csrc[e+1];
        int s2 = g_csrc[e+2], s3 = g_csrc[e+3];
        float4 v0 = __ldg((const float4*)y + (long)s0 * D4 + c);
        float4 v1 = __ldg((const float4*)y + (long)s1 * D4 + c);
        float4 v2 = __ldg((const float4*)y + (long)s2 * D4 + c);
        float4 v3 = __ldg((const float4*)y + (long)s3 * D4 + c);
        acc.x += (v0.x + v1.x) + (v2.x + v3.x);
        acc.y += (v0.y + v1.y) + (v2.y + v3.y);
        acc.z += (v0.z + v1.z) + (v2.z + v3.z);
        acc.w += (v0.w + v1.w) + (v2.w + v3.w);
    }
    for (; e < end; e++) {
        int s = g_csrc[e];
        float4 v = __ldg((const float4*)y + (long)s * D4 + c);
        acc.x += v.x; acc.y += v.y; acc.z += v.z; acc.w += v.w;
    }
    if constexpr (FINAL) {
        float4 zz = ((const float4*)z)[t];
        float4 xx = __ldg((const float4*)ax + t);
        acc.x += zz.x + xx.x;
        acc.y += zz.y + xx.y;
        acc.z += zz.z + xx.z;
        acc.w += zz.w + xx.w;
    }
    ((float4*)outp)[t] = acc;
}

__global__ void gather1_kernel(int N) {
    gather_body<8,  false>(g_y1, g_agg1, nullptr, nullptr, N);
}
__global__ void gather2_kernel(int N) {
    gather_body<12, false>(g_y2, g_agg2, nullptr, nullptr, N);
}
__global__ void gather3_kernel(const float* __restrict__ ax,
                               float* __restrict__ out, int N) {
    gather_body<4,  true>(g_y3, out, g_z3, ax, N);
}

// ---------------- launch ----------------
extern "C" void kernel_launch(void* const* d_in, const int* in_sizes, int n_in,
                              void* d_out, int out_size)
{
    (void)n_in; (void)out_size;
    const float* x   = (const float*)d_in[0];
    const int*   ei  = (const int*)d_in[1];     // int32 (JAX x64 disabled)
    const float* ax  = (const float*)d_in[2];
    const float* lf  = (const float*)d_in[3];
    const float* W1r = (const float*)d_in[4];
    const float* b1  = (const float*)d_in[5];
    const float* W1o = (const float*)d_in[6];
    const float* W2r = (const float*)d_in[7];
    const float* b2  = (const float*)d_in[8];
    const float* W2o = (const float*)d_in[9];
    const float* W3r = (const float*)d_in[10];
    const float* b3  = (const float*)d_in[11];
    const float* W3o = (const float*)d_in[12];

    int N = in_sizes[0] / 48;
    int E = in_sizes[1] / 2;

    // CSR build (once per call; reused by all 3 layers)
    zero_cnt_kernel<<<CDIV(N, 256), 256>>>(N);
    count_kernel<<<CDIV(E, 256), 256>>>(ei, E, N);
    scan_kernel<<<1, 1024>>>(N, E);
    fill_kernel<<<CDIV(E, 256), 256>>>(ei, E, N);

    gemm1_kernel<<<CDIV(N, 128), 128>>>(x, ax, W1r, W1o, b1, N);
    gather1_kernel<<<CDIV(N * 8, 256), 256>>>(N);

    gemm2_kernel<<<CDIV(N, 128), 128>>>(lf, W2r, W2o, b2, N);
    gather2_kernel<<<CDIV(N * 12, 256), 256>>>(N);

    gemm3_kernel<<<CDIV(N, 128), 128>>>(W3r, W3o, b3, N);
    gather3_kernel<<<CDIV(N * 4, 256), 256>>>(ax, (float*)d_out, N);
}